// round 2
// baseline (speedup 1.0000x reference)
#include <cuda_runtime.h>
#include <math.h>

// Problem constants
#define NB   64      // batch
#define NT   1024    // T
#define AD   128     // ATTN_DIM
#define RD   1024    // RNN_DIM
#define ED   512     // ENC_DIM
#define NF   32      // N_FILT
#define KSZ  31      // KSIZE
#define PADW 15

// ---------------- scratch (device globals: no allocation allowed) ----------
// Extended transposed weight: rows 0..511 = W_key^T (k-major), rows 512..543 = W_loc_proj^T
__device__ float g_WkT[ED + NF][AD];          // 544 x 128
__device__ float g_qproj[NB][AD];             // 64 x 128
__device__ float g_scores[NB][NT];            // 64 x 1024
__device__ float g_partial[NB][4][ED];        // attn@values partials

// ---------------------------------------------------------------------------
// Prep 1: build g_WkT (transpose W_key and W_loc_proj into k-major layout)
__global__ void k_prep_wt(const float* __restrict__ W_key,
                          const float* __restrict__ W_loc_proj) {
    int idx = blockIdx.x * blockDim.x + threadIdx.x;   // over 544*128
    if (idx >= (ED + NF) * AD) return;
    int k = idx >> 7;
    int a = idx & 127;
    float v = (k < ED) ? W_key[a * ED + k] : W_loc_proj[a * NF + (k - ED)];
    g_WkT[k][a] = v;
}

// ---------------------------------------------------------------------------
// Prep 2: q_proj[b][a] = sum_e query[b][e] * W_query[a][e]
__global__ __launch_bounds__(128) void k_qproj(const float* __restrict__ query,
                                               const float* __restrict__ W_query) {
    __shared__ float q_s[RD];
    int b = blockIdx.x, tid = threadIdx.x;
    #pragma unroll
    for (int i = 0; i < RD / 128; i++)
        q_s[i * 128 + tid] = query[b * RD + i * 128 + tid];
    __syncthreads();
    const float4* wr = (const float4*)(W_query + (size_t)tid * RD);
    float acc = 0.f;
    #pragma unroll 8
    for (int e4 = 0; e4 < RD / 4; e4++) {
        float4 w = wr[e4];
        float4 q = *(const float4*)&q_s[e4 * 4];
        acc += w.x * q.x + w.y * q.y + w.z * q.z + w.w * q.w;
    }
    g_qproj[b][tid] = acc;
}

// ---------------------------------------------------------------------------
// Scores: fused [conv1d -> loc_proj -> + k_proj GEMM -> + q_proj -> tanh ->
//         dot(W_attn) -> mask] per (b, 64-t tile).
// GEMM view: pre[t][a] = sum_{k<512} keys[b,t,k]*WkT[k][a]
//                      + sum_{f<32} loc[t][f]*WkT[512+f][a]
__global__ __launch_bounds__(256) void k_scores(
    const float* __restrict__ keys,
    const float* __restrict__ awc,
    const float* __restrict__ W_loc_conv,
    const float* __restrict__ W_attn,
    const unsigned char* __restrict__ mask)
{
    __shared__ float keys_s[64][32];      // [t][k-chunk]
    __shared__ float wkey_s[32][128];     // [k][a]
    __shared__ float loc_s[64][32];       // [t][f]
    __shared__ float awc_s[96];
    __shared__ float Wc_s[NF][KSZ];
    __shared__ float qp_s[AD];
    __shared__ float wattn_s[AD];

    const int b  = blockIdx.y;
    const int t0 = blockIdx.x * 64;
    const int tid = threadIdx.x;

    // stage small operands
    if (tid < 96) {
        int g = t0 - PADW + tid;
        awc_s[tid] = (g >= 0 && g < NT && tid < 94) ? awc[b * NT + g] : 0.f;
    }
    if (tid < AD) {
        qp_s[tid]    = g_qproj[b][tid];
        wattn_s[tid] = W_attn[tid];
    }
    for (int i = tid; i < NF * KSZ; i += 256)
        Wc_s[i / KSZ][i % KSZ] = W_loc_conv[i];
    __syncthreads();

    // location conv: loc[t][f] = sum_k awc[t0+t+k-15] * Wc[f][k]
    #pragma unroll
    for (int i = 0; i < 8; i++) {
        int o = tid + 256 * i;            // 0..2047
        int t = o >> 5, f = o & 31;
        float s = 0.f;
        #pragma unroll
        for (int k = 0; k < KSZ; k++) s += awc_s[t + k] * Wc_s[f][k];
        loc_s[t][f] = s;
    }
    __syncthreads();

    const int tx = tid & 15, ty = tid >> 4;
    const int a0 = tx * 8, tA = ty * 4;

    float acc[4][8];
    #pragma unroll
    for (int j = 0; j < 4; j++)
        #pragma unroll
        for (int i = 0; i < 8; i++) acc[j][i] = 0.f;

    // main K loop: 16 chunks of keys (K=512) + 1 chunk of loc features (K=32)
    for (int kc = 0; kc < 17; kc++) {
        if (kc < 16) {
            #pragma unroll
            for (int i = 0; i < 2; i++) {
                int idx = tid + 256 * i;          // 512 float4s
                int r = idx >> 3, c = (idx & 7) * 4;
                *(float4*)&keys_s[r][c] =
                    *(const float4*)&keys[((size_t)(b * NT + t0 + r)) * ED + kc * 32 + c];
            }
        } else {
            #pragma unroll
            for (int i = 0; i < 2; i++) {
                int idx = tid + 256 * i;
                int r = idx >> 3, c = (idx & 7) * 4;
                *(float4*)&keys_s[r][c] = *(const float4*)&loc_s[r][c];
            }
        }
        #pragma unroll
        for (int i = 0; i < 4; i++) {
            int idx = tid + 256 * i;              // 1024 float4s
            int r = idx >> 5, c = (idx & 31) * 4;
            *(float4*)&wkey_s[r][c] = *(const float4*)&g_WkT[kc * 32 + r][c];
        }
        __syncthreads();

        #pragma unroll
        for (int k4 = 0; k4 < 32; k4 += 4) {
            float4 kv[4];
            #pragma unroll
            for (int j = 0; j < 4; j++)
                kv[j] = *(const float4*)&keys_s[tA + j][k4];
            #pragma unroll
            for (int kk = 0; kk < 4; kk++) {
                float4 wlo = *(const float4*)&wkey_s[k4 + kk][a0];
                float4 whi = *(const float4*)&wkey_s[k4 + kk][a0 + 4];
                #pragma unroll
                for (int j = 0; j < 4; j++) {
                    float kval = (kk == 0) ? kv[j].x : (kk == 1) ? kv[j].y
                               : (kk == 2) ? kv[j].z : kv[j].w;
                    acc[j][0] += kval * wlo.x;  acc[j][1] += kval * wlo.y;
                    acc[j][2] += kval * wlo.z;  acc[j][3] += kval * wlo.w;
                    acc[j][4] += kval * whi.x;  acc[j][5] += kval * whi.y;
                    acc[j][6] += kval * whi.z;  acc[j][7] += kval * whi.w;
                }
            }
        }
        __syncthreads();
    }

    // epilogue: tanh + dot with W_attn, reduce 16 a-lanes, mask, store score
    #pragma unroll
    for (int j = 0; j < 4; j++) {
        float s = 0.f;
        #pragma unroll
        for (int i = 0; i < 8; i++)
            s += wattn_s[a0 + i] * tanhf(acc[j][i] + qp_s[a0 + i]);
        #pragma unroll
        for (int off = 8; off > 0; off >>= 1)
            s += __shfl_down_sync(0xffffffffu, s, off, 32);
        if (tx == 0) {
            int t = t0 + tA + j;
            float sc = s;
            if (mask[b * NT + t]) sc = -INFINITY;
            g_scores[b][t] = sc;
        }
    }
}

// ---------------------------------------------------------------------------
// Softmax over T per batch; writes attn directly into d_out region.
__global__ __launch_bounds__(256) void k_softmax(float* __restrict__ attn_out) {
    __shared__ float red[256];
    int b = blockIdx.x, tid = threadIdx.x;
    float v[4];
    float m = -INFINITY;
    #pragma unroll
    for (int i = 0; i < 4; i++) {
        v[i] = g_scores[b][i * 256 + tid];
        m = fmaxf(m, v[i]);
    }
    red[tid] = m; __syncthreads();
    for (int s = 128; s > 0; s >>= 1) {
        if (tid < s) red[tid] = fmaxf(red[tid], red[tid + s]);
        __syncthreads();
    }
    m = red[0]; __syncthreads();
    float sum = 0.f;
    #pragma unroll
    for (int i = 0; i < 4; i++) { v[i] = __expf(v[i] - m); sum += v[i]; }
    red[tid] = sum; __syncthreads();
    for (int s = 128; s > 0; s >>= 1) {
        if (tid < s) red[tid] += red[tid + s];
        __syncthreads();
    }
    float inv = 1.f / red[0];
    #pragma unroll
    for (int i = 0; i < 4; i++)
        attn_out[b * NT + i * 256 + tid] = v[i] * inv;
}

// ---------------------------------------------------------------------------
// attn @ values (partial over T chunks of 256). HBM-bound: reads all of values.
__global__ __launch_bounds__(256) void k_av(const float* __restrict__ values,
                                            const float* __restrict__ attn) {
    __shared__ float at_s[256];
    int ts = blockIdx.x, b = blockIdx.y, tid = threadIdx.x;
    at_s[tid] = attn[b * NT + ts * 256 + tid];
    __syncthreads();
    const float* vp = values + ((size_t)b * NT + ts * 256) * ED;
    float a0 = 0.f, a1 = 0.f;
    #pragma unroll 4
    for (int t = 0; t < 256; t++) {
        float w = at_s[t];
        a0 += w * vp[(size_t)t * ED + tid];
        a1 += w * vp[(size_t)t * ED + 256 + tid];
    }
    g_partial[b][ts][tid]       = a0;
    g_partial[b][ts][256 + tid] = a1;
}

// ---------------------------------------------------------------------------
// context[b][f] = sum_e av[b][e] * W_value[f][e]
__global__ __launch_bounds__(128) void k_context(const float* __restrict__ W_value,
                                                 float* __restrict__ ctx) {
    __shared__ float av_s[ED];
    int fc = blockIdx.x, b = blockIdx.y, tid = threadIdx.x;
    for (int i = tid; i < ED; i += 128)
        av_s[i] = g_partial[b][0][i] + g_partial[b][1][i]
                + g_partial[b][2][i] + g_partial[b][3][i];
    __syncthreads();
    int f = fc * 128 + tid;
    const float4* wr = (const float4*)(W_value + (size_t)f * ED);
    float acc = 0.f;
    #pragma unroll 8
    for (int e4 = 0; e4 < ED / 4; e4++) {
        float4 w = wr[e4];
        float4 a = *(const float4*)&av_s[e4 * 4];
        acc += w.x * a.x + w.y * a.y + w.z * a.z + w.w * a.w;
    }
    ctx[b * ED + f] = acc;
}

// ---------------------------------------------------------------------------
extern "C" void kernel_launch(void* const* d_in, const int* in_sizes, int n_in,
                              void* d_out, int out_size) {
    const float* query         = (const float*)d_in[0];
    const float* keys          = (const float*)d_in[1];
    const float* values        = (const float*)d_in[2];
    const float* awc           = (const float*)d_in[3];
    const unsigned char* mask  = (const unsigned char*)d_in[4];
    const float* W_loc_conv    = (const float*)d_in[5];
    // W_loc_proj = d_in[6]
    const float* W_loc_proj    = (const float*)d_in[6];
    const float* W_query       = (const float*)d_in[7];
    const float* W_key         = (const float*)d_in[8];
    const float* W_value       = (const float*)d_in[9];
    const float* W_attn        = (const float*)d_in[10];

    float* out      = (float*)d_out;
    float* ctx_out  = out;                 // context: 64*512
    float* attn_out = out + NB * ED;       // attn:    64*1024

    k_prep_wt<<<((ED + NF) * AD + 255) / 256, 256>>>(W_key, W_loc_proj);
    k_qproj  <<<NB, 128>>>(query, W_query);
    k_scores <<<dim3(NT / 64, NB), 256>>>(keys, awc, W_loc_conv, W_attn, mask);
    k_softmax<<<NB, 256>>>(attn_out);
    k_av     <<<dim3(4, NB), 256>>>(values, attn_out);
    k_context<<<dim3(4, NB), 128>>>(W_value, ctx_out);
}

// round 3
// speedup vs baseline: 1.6814x; 1.6814x over previous
#include <cuda_runtime.h>
#include <math.h>

// Problem constants
#define NB   64      // batch
#define NT   1024    // T
#define AD   128     // ATTN_DIM
#define RD   1024    // RNN_DIM
#define ED   512     // ENC_DIM
#define NF   32      // N_FILT
#define KSZ  31      // KSIZE
#define PADW 15

#define NKC  17      // K chunks of 32 (512 keys + 32 loc)

// ---------------- scratch (device globals: no allocation allowed) ----------
__device__ float g_WkT[ED + NF][AD];          // 544 x 128 (k-major)
__device__ float g_qproj[NB][AD];
__device__ float g_scores[NB][NT];
__device__ float g_partial[NB][8][ED];        // attn@values partials

// ---------------------------------------------------------------------------
__global__ void k_prep_wt(const float* __restrict__ W_key,
                          const float* __restrict__ W_loc_proj) {
    int idx = blockIdx.x * blockDim.x + threadIdx.x;
    if (idx >= (ED + NF) * AD) return;
    int k = idx >> 7, a = idx & 127;
    float v = (k < ED) ? W_key[a * ED + k] : W_loc_proj[a * NF + (k - ED)];
    g_WkT[k][a] = v;
}

// ---------------------------------------------------------------------------
__global__ __launch_bounds__(128) void k_qproj(const float* __restrict__ query,
                                               const float* __restrict__ W_query) {
    __shared__ float q_s[RD];
    int b = blockIdx.x, tid = threadIdx.x;
    #pragma unroll
    for (int i = 0; i < RD / 128; i++)
        q_s[i * 128 + tid] = query[b * RD + i * 128 + tid];
    __syncthreads();
    const float4* wr = (const float4*)(W_query + (size_t)tid * RD);
    float acc = 0.f;
    #pragma unroll 8
    for (int e4 = 0; e4 < RD / 4; e4++) {
        float4 w = wr[e4];
        float4 q = *(const float4*)&q_s[e4 * 4];
        acc += w.x * q.x + w.y * q.y + w.z * q.z + w.w * q.w;
    }
    g_qproj[b][tid] = acc;
}

// ---------------------------------------------------------------------------
// tf32 helpers
__device__ __forceinline__ float to_tf32(float x) {
    unsigned u;
    asm("cvt.rna.tf32.f32 %0, %1;" : "=r"(u) : "f"(x));
    return __uint_as_float(u);
}

__device__ __forceinline__ void mma_tf32(float d[4], const unsigned a[4],
                                         unsigned b0, unsigned b1) {
    asm volatile(
        "mma.sync.aligned.m16n8k8.row.col.f32.tf32.tf32.f32 "
        "{%0,%1,%2,%3}, {%4,%5,%6,%7}, {%8,%9}, {%0,%1,%2,%3};"
        : "+f"(d[0]), "+f"(d[1]), "+f"(d[2]), "+f"(d[3])
        : "r"(a[0]), "r"(a[1]), "r"(a[2]), "r"(a[3]), "r"(b0), "r"(b1));
}

// ---------------------------------------------------------------------------
// Fused scores: [conv1d loc -> loc_proj | keys GEMM] via tf32 MMA,
// epilogue: +q_proj -> tanh -> dot W_attn -> mask -> g_scores.
// Block: 256 threads (8 warps), tile M=128 t-rows x N=128 a-cols, K=544.
#define KS_PAD 36    // keys_s row stride (floats): banks 4g+tg distinct
#define WK_PAD 136   // wkey_s row stride: banks 8tg+g distinct

__global__ __launch_bounds__(256, 2) void k_scores(
    const float* __restrict__ keys,
    const float* __restrict__ awc,
    const float* __restrict__ W_loc_conv,
    const float* __restrict__ W_attn,
    const unsigned char* __restrict__ mask)
{
    __shared__ float keys_s[128 * KS_PAD];   // 18.4 KB
    __shared__ float wkey_s[32 * WK_PAD];    // 17.4 KB
    __shared__ float awc_s[158];
    __shared__ float Wc_s[NF][KSZ];
    __shared__ float qp_s[AD];
    __shared__ float wattn_s[AD];
    __shared__ float sred[2][128];

    const int b   = blockIdx.y;
    const int t0  = blockIdx.x * 128;
    const int tid = threadIdx.x;
    const int lane = tid & 31, w = tid >> 5;
    const int g = lane >> 2, tg = lane & 3;   // mma fragment coords
    const int Mb = (w & 3) * 32;              // warp M base (t)
    const int Nb = (w >> 2) * 64;             // warp N base (a)

    // stage small operands
    if (tid < 158) {
        int gi = t0 - PADW + tid;
        awc_s[tid] = (gi >= 0 && gi < NT) ? awc[b * NT + gi] : 0.f;
    }
    if (tid < AD) { qp_s[tid] = g_qproj[b][tid]; wattn_s[tid] = W_attn[tid]; }
    for (int i = tid; i < NF * KSZ; i += 256)
        Wc_s[i / KSZ][i % KSZ] = W_loc_conv[i];
    __syncthreads();

    float4 ka[4], wa[4];   // double-buffer registers for next chunk

    // prologue: fetch chunk 0
    #pragma unroll
    for (int j = 0; j < 4; j++) {
        int idx = tid + 256 * j;
        { int r = idx >> 3, c = (idx & 7) << 2;
          ka[j] = *(const float4*)&keys[((size_t)(b * NT + t0 + r)) * ED + c]; }
        { int r = idx >> 5, c = (idx & 31) << 2;
          wa[j] = *(const float4*)&g_WkT[r][c]; }
    }

    float acc[2][8][4];
    #pragma unroll
    for (int mt = 0; mt < 2; mt++)
        #pragma unroll
        for (int nt = 0; nt < 8; nt++)
            #pragma unroll
            for (int ci = 0; ci < 4; ci++) acc[mt][nt][ci] = 0.f;

    for (int kc = 0; kc < NKC; kc++) {
        __syncthreads();   // previous smem chunk fully consumed
        // store staged regs -> smem with tf32 rounding
        #pragma unroll
        for (int j = 0; j < 4; j++) {
            int idx = tid + 256 * j;
            { int r = idx >> 3, c = (idx & 7) << 2;
              float4 v = ka[j];
              v.x = to_tf32(v.x); v.y = to_tf32(v.y);
              v.z = to_tf32(v.z); v.w = to_tf32(v.w);
              *(float4*)&keys_s[r * KS_PAD + c] = v; }
            { int r = idx >> 5, c = (idx & 31) << 2;
              float4 v = wa[j];
              v.x = to_tf32(v.x); v.y = to_tf32(v.y);
              v.z = to_tf32(v.z); v.w = to_tf32(v.w);
              *(float4*)&wkey_s[r * WK_PAD + c] = v; }
        }
        __syncthreads();

        // prefetch next chunk while MMA runs on this one
        if (kc < 15) {
            #pragma unroll
            for (int j = 0; j < 4; j++) {
                int idx = tid + 256 * j;
                { int r = idx >> 3, c = (idx & 7) << 2;
                  ka[j] = *(const float4*)
                      &keys[((size_t)(b * NT + t0 + r)) * ED + (kc + 1) * 32 + c]; }
                { int r = idx >> 5, c = (idx & 31) << 2;
                  wa[j] = *(const float4*)&g_WkT[(kc + 1) * 32 + r][c]; }
            }
        } else if (kc == 15) {
            // chunk 16 = location features: conv1d(awc) per (t, filter)
            #pragma unroll
            for (int j = 0; j < 4; j++) {
                int idx = tid + 256 * j;
                int r = idx >> 3, c = (idx & 7) << 2;
                float s0 = 0.f, s1 = 0.f, s2 = 0.f, s3 = 0.f;
                #pragma unroll
                for (int k = 0; k < KSZ; k++) {
                    float av = awc_s[r + k];
                    s0 += av * Wc_s[c + 0][k];
                    s1 += av * Wc_s[c + 1][k];
                    s2 += av * Wc_s[c + 2][k];
                    s3 += av * Wc_s[c + 3][k];
                }
                ka[j] = make_float4(s0, s1, s2, s3);
                int r2 = idx >> 5, c2 = (idx & 31) << 2;
                wa[j] = *(const float4*)&g_WkT[ED + r2][c2];
            }
        }

        // MMA on current chunk: 4 k8-steps
        #pragma unroll
        for (int k8 = 0; k8 < 4; k8++) {
            int kb = k8 * 8;
            unsigned a[2][4];
            #pragma unroll
            for (int mt = 0; mt < 2; mt++) {
                int rb = Mb + mt * 16;
                a[mt][0] = __float_as_uint(keys_s[(rb + g    ) * KS_PAD + kb + tg    ]);
                a[mt][1] = __float_as_uint(keys_s[(rb + g + 8) * KS_PAD + kb + tg    ]);
                a[mt][2] = __float_as_uint(keys_s[(rb + g    ) * KS_PAD + kb + tg + 4]);
                a[mt][3] = __float_as_uint(keys_s[(rb + g + 8) * KS_PAD + kb + tg + 4]);
            }
            #pragma unroll
            for (int nt = 0; nt < 8; nt++) {
                unsigned b0 = __float_as_uint(wkey_s[(kb + tg    ) * WK_PAD + Nb + nt * 8 + g]);
                unsigned b1 = __float_as_uint(wkey_s[(kb + tg + 4) * WK_PAD + Nb + nt * 8 + g]);
                mma_tf32(acc[0][nt], a[0], b0, b1);
                mma_tf32(acc[1][nt], a[1], b0, b1);
            }
        }
    }

    // epilogue: tanh + W_attn dot, reduce over a, mask, store scores
    #pragma unroll
    for (int mt = 0; mt < 2; mt++) {
        #pragma unroll
        for (int h = 0; h < 2; h++) {
            float p = 0.f;
            #pragma unroll
            for (int nt = 0; nt < 8; nt++) {
                int col = Nb + nt * 8 + 2 * tg;
                p += wattn_s[col]     * tanhf(acc[mt][nt][2 * h]     + qp_s[col]);
                p += wattn_s[col + 1] * tanhf(acc[mt][nt][2 * h + 1] + qp_s[col + 1]);
            }
            p += __shfl_xor_sync(0xffffffffu, p, 1);
            p += __shfl_xor_sync(0xffffffffu, p, 2);
            if (tg == 0) {
                int row = Mb + mt * 16 + g + 8 * h;
                sred[w >> 2][row] = p;
            }
        }
    }
    __syncthreads();
    if (tid < 128) {
        int t = t0 + tid;
        float sc = sred[0][tid] + sred[1][tid];
        if (mask[b * NT + t]) sc = -INFINITY;
        g_scores[b][t] = sc;
    }
}

// ---------------------------------------------------------------------------
__global__ __launch_bounds__(256) void k_softmax(float* __restrict__ attn_out) {
    __shared__ float red[256];
    int b = blockIdx.x, tid = threadIdx.x;
    float v[4];
    float m = -INFINITY;
    #pragma unroll
    for (int i = 0; i < 4; i++) {
        v[i] = g_scores[b][i * 256 + tid];
        m = fmaxf(m, v[i]);
    }
    red[tid] = m; __syncthreads();
    for (int s = 128; s > 0; s >>= 1) {
        if (tid < s) red[tid] = fmaxf(red[tid], red[tid + s]);
        __syncthreads();
    }
    m = red[0]; __syncthreads();
    float sum = 0.f;
    #pragma unroll
    for (int i = 0; i < 4; i++) { v[i] = __expf(v[i] - m); sum += v[i]; }
    red[tid] = sum; __syncthreads();
    for (int s = 128; s > 0; s >>= 1) {
        if (tid < s) red[tid] += red[tid + s];
        __syncthreads();
    }
    float inv = 1.f / red[0];
    #pragma unroll
    for (int i = 0; i < 4; i++)
        attn_out[b * NT + i * 256 + tid] = v[i] * inv;
}

// ---------------------------------------------------------------------------
// attn @ values, vectorized float4, 8 partials per batch. HBM-bound.
__global__ __launch_bounds__(256) void k_av(const float* __restrict__ values,
                                            const float* __restrict__ attn) {
    __shared__ float at_s[256];
    int ts = blockIdx.x, b = blockIdx.y, tid = threadIdx.x;
    at_s[tid] = attn[b * NT + ts * 256 + tid];
    __syncthreads();
    int cg = tid & 127;          // float4 column group (512/4 = 128)
    int half = tid >> 7;         // splits 256 t into 2x128
    const float4* vp = (const float4*)
        (values + ((size_t)(b * NT + ts * 256 + half * 128)) * ED);
    float4 acc = make_float4(0.f, 0.f, 0.f, 0.f);
    #pragma unroll 4
    for (int t = 0; t < 128; t++) {
        float wv = at_s[half * 128 + t];
        float4 v = vp[(size_t)t * (ED / 4) + cg];
        acc.x += wv * v.x; acc.y += wv * v.y;
        acc.z += wv * v.z; acc.w += wv * v.w;
    }
    *(float4*)&g_partial[b][ts * 2 + half][cg * 4] = acc;
}

// ---------------------------------------------------------------------------
__global__ __launch_bounds__(128) void k_context(const float* __restrict__ W_value,
                                                 float* __restrict__ ctx) {
    __shared__ float av_s[ED];
    int fc = blockIdx.x, b = blockIdx.y, tid = threadIdx.x;
    for (int i = tid; i < ED; i += 128) {
        float s = 0.f;
        #pragma unroll
        for (int p = 0; p < 8; p++) s += g_partial[b][p][i];
        av_s[i] = s;
    }
    __syncthreads();
    int f = fc * 128 + tid;
    const float4* wr = (const float4*)(W_value + (size_t)f * ED);
    float acc = 0.f;
    #pragma unroll 8
    for (int e4 = 0; e4 < ED / 4; e4++) {
        float4 wv = wr[e4];
        float4 a = *(const float4*)&av_s[e4 * 4];
        acc += wv.x * a.x + wv.y * a.y + wv.z * a.z + wv.w * a.w;
    }
    ctx[b * ED + f] = acc;
}

// ---------------------------------------------------------------------------
extern "C" void kernel_launch(void* const* d_in, const int* in_sizes, int n_in,
                              void* d_out, int out_size) {
    const float* query        = (const float*)d_in[0];
    const float* keys         = (const float*)d_in[1];
    const float* values       = (const float*)d_in[2];
    const float* awc          = (const float*)d_in[3];
    const unsigned char* mask = (const unsigned char*)d_in[4];
    const float* W_loc_conv   = (const float*)d_in[5];
    const float* W_loc_proj   = (const float*)d_in[6];
    const float* W_query      = (const float*)d_in[7];
    const float* W_key        = (const float*)d_in[8];
    const float* W_value      = (const float*)d_in[9];
    const float* W_attn       = (const float*)d_in[10];

    float* out      = (float*)d_out;
    float* ctx_out  = out;                 // context: 64*512
    float* attn_out = out + NB * ED;       // attn:    64*1024

    k_prep_wt<<<((ED + NF) * AD + 255) / 256, 256>>>(W_key, W_loc_proj);
    k_qproj  <<<NB, 128>>>(query, W_query);
    k_scores <<<dim3(NT / 128, NB), 256>>>(keys, awc, W_loc_conv, W_attn, mask);
    k_softmax<<<NB, 256>>>(attn_out);
    k_av     <<<dim3(4, NB), 256>>>(values, attn_out);
    k_context<<<dim3(4, NB), 128>>>(W_value, ctx_out);
}

// round 4
// speedup vs baseline: 2.2127x; 1.3160x over previous
#include <cuda_runtime.h>
#include <math.h>

// Problem constants
#define NB   64      // batch
#define NT   1024    // T
#define AD   128     // ATTN_DIM
#define RD   1024    // RNN_DIM
#define ED   512     // ENC_DIM
#define NF   32      // N_FILT
#define KSZ  31      // KSIZE
#define PADW 15

// ---------------- scratch (device globals: no allocation allowed) ----------
__device__ float g_WkT[ED + NF][AD];          // 544 x 128 (k-major)
__device__ float g_qproj[NB][AD];
__device__ float g_scores[NB][NT];
__device__ float g_partial[NB][8][ED];        // attn@values partials

// ---------------------------------------------------------------------------
// Fused prep: blocks [0,544) transpose W_key/W_loc_proj, blocks [544,608) qproj
__global__ __launch_bounds__(128) void k_prep(const float* __restrict__ query,
                                              const float* __restrict__ W_query,
                                              const float* __restrict__ W_key,
                                              const float* __restrict__ W_loc_proj) {
    int tid = threadIdx.x;
    if (blockIdx.x < ED + NF) {
        int k = blockIdx.x, a = tid;
        g_WkT[k][a] = (k < ED) ? W_key[a * ED + k] : W_loc_proj[a * NF + (k - ED)];
        return;
    }
    __shared__ float q_s[RD];
    int b = blockIdx.x - (ED + NF);
    #pragma unroll
    for (int i = 0; i < RD / 128; i++)
        q_s[i * 128 + tid] = query[b * RD + i * 128 + tid];
    __syncthreads();
    const float4* wr = (const float4*)(W_query + (size_t)tid * RD);
    float acc = 0.f;
    #pragma unroll 8
    for (int e4 = 0; e4 < RD / 4; e4++) {
        float4 w = wr[e4];
        float4 q = *(const float4*)&q_s[e4 * 4];
        acc += w.x * q.x + w.y * q.y + w.z * q.z + w.w * q.w;
    }
    g_qproj[b][tid] = acc;
}

// ---------------------------------------------------------------------------
__device__ __forceinline__ void mma_tf32(float d[4], const unsigned a[4],
                                         unsigned b0, unsigned b1) {
    asm volatile(
        "mma.sync.aligned.m16n8k8.row.col.f32.tf32.tf32.f32 "
        "{%0,%1,%2,%3}, {%4,%5,%6,%7}, {%8,%9}, {%0,%1,%2,%3};"
        : "+f"(d[0]), "+f"(d[1]), "+f"(d[2]), "+f"(d[3])
        : "r"(a[0]), "r"(a[1]), "r"(a[2]), "r"(a[3]), "r"(b0), "r"(b1));
}

__device__ __forceinline__ void cp16(unsigned dst, const void* src) {
    asm volatile("cp.async.ca.shared.global [%0], [%1], 16;" :: "r"(dst), "l"(src));
}
__device__ __forceinline__ void cp_commit() {
    asm volatile("cp.async.commit_group;");
}

// ---------------------------------------------------------------------------
// Fused scores: 2-stage cp.async pipeline, tf32 MMA, epilogue tanh+dot+mask.
// Block: 256 threads (8 warps), tile M=128 t-rows x N=128 a-cols, K=544.
#define KS_PAD 36            // keys_s row stride (floats)
#define WK_PAD 136           // wkey_s row stride (floats)
#define KEYS_ST (128 * KS_PAD)
#define WK_ST   (32 * WK_PAD)
#define DYN_SMEM_BYTES ((2 * KEYS_ST + 2 * WK_ST) * 4)

__global__ __launch_bounds__(256, 2) void k_scores(
    const float* __restrict__ keys,
    const float* __restrict__ awc,
    const float* __restrict__ W_loc_conv,
    const float* __restrict__ W_attn,
    const unsigned char* __restrict__ mask)
{
    extern __shared__ float dsm[];
    float* keys_st[2] = { dsm, dsm + KEYS_ST };
    float* wkey_st[2] = { dsm + 2 * KEYS_ST, dsm + 2 * KEYS_ST + WK_ST };

    __shared__ float awc_s[158];
    __shared__ float Wc_s[NF][KSZ];
    __shared__ float qp_s[AD];
    __shared__ float wattn_s[AD];
    __shared__ float sred[2][128];

    const int b   = blockIdx.y;
    const int t0  = blockIdx.x * 128;
    const int tid = threadIdx.x;
    const int lane = tid & 31, w = tid >> 5;
    const int g = lane >> 2, tg = lane & 3;
    const int Mb = (w & 3) * 32;
    const int Nb = (w >> 2) * 64;

    // precompute cp.async smem destinations + global sources for this thread
    const int kr = tid >> 3, kcol = (tid & 7) << 2;     // keys: 4 rows apart per j
    const int wr_ = tid >> 5, wcol = (tid & 31) << 2;   // wkey: 8 rows apart per j
    const float* keys_base = keys + ((size_t)(b * NT + t0 + kr)) * ED + kcol;

    // stage small operands
    if (tid < 158) {
        int gi = t0 - PADW + tid;
        awc_s[tid] = (gi >= 0 && gi < NT) ? awc[b * NT + gi] : 0.f;
    }
    if (tid < AD) { qp_s[tid] = g_qproj[b][tid]; wattn_s[tid] = W_attn[tid]; }
    for (int i = tid; i < NF * KSZ; i += 256)
        Wc_s[i / KSZ][i % KSZ] = W_loc_conv[i];

    // issue chunks 0 and 1
    #pragma unroll
    for (int s = 0; s < 2; s++) {
        #pragma unroll
        for (int j = 0; j < 4; j++) {
            cp16((unsigned)__cvta_generic_to_shared(
                     &keys_st[s][(kr + 32 * j) * KS_PAD + kcol]),
                 keys_base + (size_t)(32 * j) * ED + s * 32);
            cp16((unsigned)__cvta_generic_to_shared(
                     &wkey_st[s][(wr_ + 8 * j) * WK_PAD + wcol]),
                 &g_WkT[s * 32 + wr_ + 8 * j][wcol]);
        }
        cp_commit();
    }

    float acc[2][8][4];
    #pragma unroll
    for (int mt = 0; mt < 2; mt++)
        #pragma unroll
        for (int nt = 0; nt < 8; nt++)
            #pragma unroll
            for (int ci = 0; ci < 4; ci++) acc[mt][nt][ci] = 0.f;

    for (int kc = 0; kc < 16; kc++) {
        if (kc < 15) asm volatile("cp.async.wait_group 1;");
        else         asm volatile("cp.async.wait_group 0;");
        __syncthreads();

        const float* ks = keys_st[kc & 1];
        const float* ws = wkey_st[kc & 1];

        #pragma unroll
        for (int k8 = 0; k8 < 4; k8++) {
            int kb = k8 * 8;
            unsigned a[2][4];
            #pragma unroll
            for (int mt = 0; mt < 2; mt++) {
                int rb = Mb + mt * 16;
                a[mt][0] = __float_as_uint(ks[(rb + g    ) * KS_PAD + kb + tg    ]);
                a[mt][1] = __float_as_uint(ks[(rb + g + 8) * KS_PAD + kb + tg    ]);
                a[mt][2] = __float_as_uint(ks[(rb + g    ) * KS_PAD + kb + tg + 4]);
                a[mt][3] = __float_as_uint(ks[(rb + g + 8) * KS_PAD + kb + tg + 4]);
            }
            #pragma unroll
            for (int nt = 0; nt < 8; nt++) {
                unsigned b0 = __float_as_uint(ws[(kb + tg    ) * WK_PAD + Nb + nt * 8 + g]);
                unsigned b1 = __float_as_uint(ws[(kb + tg + 4) * WK_PAD + Nb + nt * 8 + g]);
                mma_tf32(acc[0][nt], a[0], b0, b1);
                mma_tf32(acc[1][nt], a[1], b0, b1);
            }
        }
        __syncthreads();

        if (kc + 2 < 16) {
            int nc = kc + 2, s = nc & 1;
            #pragma unroll
            for (int j = 0; j < 4; j++) {
                cp16((unsigned)__cvta_generic_to_shared(
                         &keys_st[s][(kr + 32 * j) * KS_PAD + kcol]),
                     keys_base + (size_t)(32 * j) * ED + nc * 32);
                cp16((unsigned)__cvta_generic_to_shared(
                         &wkey_st[s][(wr_ + 8 * j) * WK_PAD + wcol]),
                     &g_WkT[nc * 32 + wr_ + 8 * j][wcol]);
            }
        }
        cp_commit();
    }

    // ---- location-feature chunk (chunk 16) into stage 0 ----
    #pragma unroll
    for (int j = 0; j < 4; j++)
        cp16((unsigned)__cvta_generic_to_shared(
                 &wkey_st[0][(wr_ + 8 * j) * WK_PAD + wcol]),
             &g_WkT[ED + wr_ + 8 * j][wcol]);
    cp_commit();

    #pragma unroll
    for (int j = 0; j < 4; j++) {
        int idx = tid + 256 * j;
        int r = idx >> 3, c = (idx & 7) << 2;
        float s0 = 0.f, s1 = 0.f, s2 = 0.f, s3 = 0.f;
        #pragma unroll
        for (int k = 0; k < KSZ; k++) {
            float av = awc_s[r + k];
            s0 += av * Wc_s[c + 0][k];
            s1 += av * Wc_s[c + 1][k];
            s2 += av * Wc_s[c + 2][k];
            s3 += av * Wc_s[c + 3][k];
        }
        *(float4*)&keys_st[0][r * KS_PAD + c] = make_float4(s0, s1, s2, s3);
    }
    asm volatile("cp.async.wait_group 0;");
    __syncthreads();
    {
        const float* ks = keys_st[0];
        const float* ws = wkey_st[0];
        #pragma unroll
        for (int k8 = 0; k8 < 4; k8++) {
            int kb = k8 * 8;
            unsigned a[2][4];
            #pragma unroll
            for (int mt = 0; mt < 2; mt++) {
                int rb = Mb + mt * 16;
                a[mt][0] = __float_as_uint(ks[(rb + g    ) * KS_PAD + kb + tg    ]);
                a[mt][1] = __float_as_uint(ks[(rb + g + 8) * KS_PAD + kb + tg    ]);
                a[mt][2] = __float_as_uint(ks[(rb + g    ) * KS_PAD + kb + tg + 4]);
                a[mt][3] = __float_as_uint(ks[(rb + g + 8) * KS_PAD + kb + tg + 4]);
            }
            #pragma unroll
            for (int nt = 0; nt < 8; nt++) {
                unsigned b0 = __float_as_uint(ws[(kb + tg    ) * WK_PAD + Nb + nt * 8 + g]);
                unsigned b1 = __float_as_uint(ws[(kb + tg + 4) * WK_PAD + Nb + nt * 8 + g]);
                mma_tf32(acc[0][nt], a[0], b0, b1);
                mma_tf32(acc[1][nt], a[1], b0, b1);
            }
        }
    }

    // epilogue: tanh + W_attn dot, reduce over a, mask, store scores
    #pragma unroll
    for (int mt = 0; mt < 2; mt++) {
        #pragma unroll
        for (int h = 0; h < 2; h++) {
            float p = 0.f;
            #pragma unroll
            for (int nt = 0; nt < 8; nt++) {
                int col = Nb + nt * 8 + 2 * tg;
                p += wattn_s[col]     * tanhf(acc[mt][nt][2 * h]     + qp_s[col]);
                p += wattn_s[col + 1] * tanhf(acc[mt][nt][2 * h + 1] + qp_s[col + 1]);
            }
            p += __shfl_xor_sync(0xffffffffu, p, 1);
            p += __shfl_xor_sync(0xffffffffu, p, 2);
            if (tg == 0)
                sred[w >> 2][Mb + mt * 16 + g + 8 * h] = p;
        }
    }
    __syncthreads();
    if (tid < 128) {
        int t = t0 + tid;
        float sc = sred[0][tid] + sred[1][tid];
        if (mask[b * NT + t]) sc = -INFINITY;
        g_scores[b][t] = sc;
    }
}

// ---------------------------------------------------------------------------
__global__ __launch_bounds__(256) void k_softmax(float* __restrict__ attn_out) {
    __shared__ float red[256];
    int b = blockIdx.x, tid = threadIdx.x;
    float v[4];
    float m = -INFINITY;
    #pragma unroll
    for (int i = 0; i < 4; i++) {
        v[i] = g_scores[b][i * 256 + tid];
        m = fmaxf(m, v[i]);
    }
    red[tid] = m; __syncthreads();
    for (int s = 128; s > 0; s >>= 1) {
        if (tid < s) red[tid] = fmaxf(red[tid], red[tid + s]);
        __syncthreads();
    }
    m = red[0]; __syncthreads();
    float sum = 0.f;
    #pragma unroll
    for (int i = 0; i < 4; i++) { v[i] = __expf(v[i] - m); sum += v[i]; }
    red[tid] = sum; __syncthreads();
    for (int s = 128; s > 0; s >>= 1) {
        if (tid < s) red[tid] += red[tid + s];
        __syncthreads();
    }
    float inv = 1.f / red[0];
    #pragma unroll
    for (int i = 0; i < 4; i++)
        attn_out[b * NT + i * 256 + tid] = v[i] * inv;
}

// ---------------------------------------------------------------------------
// attn @ values, vectorized float4, 8 partials per batch. HBM-bound.
__global__ __launch_bounds__(256) void k_av(const float* __restrict__ values,
                                            const float* __restrict__ attn) {
    __shared__ float at_s[256];
    int ts = blockIdx.x, b = blockIdx.y, tid = threadIdx.x;
    at_s[tid] = attn[b * NT + ts * 256 + tid];
    __syncthreads();
    int cg = tid & 127;          // float4 column group
    int half = tid >> 7;
    const float4* vp = (const float4*)
        (values + ((size_t)(b * NT + ts * 256 + half * 128)) * ED);
    float4 acc = make_float4(0.f, 0.f, 0.f, 0.f);
    #pragma unroll 8
    for (int t = 0; t < 128; t++) {
        float wv = at_s[half * 128 + t];
        float4 v = vp[(size_t)t * (ED / 4) + cg];
        acc.x += wv * v.x; acc.y += wv * v.y;
        acc.z += wv * v.z; acc.w += wv * v.w;
    }
    *(float4*)&g_partial[b][ts * 2 + half][cg * 4] = acc;
}

// ---------------------------------------------------------------------------
__global__ __launch_bounds__(128) void k_context(const float* __restrict__ W_value,
                                                 float* __restrict__ ctx) {
    __shared__ float av_s[ED];
    int fc = blockIdx.x, b = blockIdx.y, tid = threadIdx.x;
    for (int i = tid; i < ED; i += 128) {
        float s = 0.f;
        #pragma unroll
        for (int p = 0; p < 8; p++) s += g_partial[b][p][i];
        av_s[i] = s;
    }
    __syncthreads();
    int f = fc * 128 + tid;
    const float4* wr = (const float4*)(W_value + (size_t)f * ED);
    float acc = 0.f;
    #pragma unroll 8
    for (int e4 = 0; e4 < ED / 4; e4++) {
        float4 wv = wr[e4];
        float4 a = *(const float4*)&av_s[e4 * 4];
        acc += wv.x * a.x + wv.y * a.y + wv.z * a.z + wv.w * a.w;
    }
    ctx[b * ED + f] = acc;
}

// ---------------------------------------------------------------------------
extern "C" void kernel_launch(void* const* d_in, const int* in_sizes, int n_in,
                              void* d_out, int out_size) {
    const float* query        = (const float*)d_in[0];
    const float* keys         = (const float*)d_in[1];
    const float* values       = (const float*)d_in[2];
    const float* awc          = (const float*)d_in[3];
    const unsigned char* mask = (const unsigned char*)d_in[4];
    const float* W_loc_conv   = (const float*)d_in[5];
    const float* W_loc_proj   = (const float*)d_in[6];
    const float* W_query      = (const float*)d_in[7];
    const float* W_key        = (const float*)d_in[8];
    const float* W_value      = (const float*)d_in[9];
    const float* W_attn       = (const float*)d_in[10];

    float* out      = (float*)d_out;
    float* ctx_out  = out;                 // context: 64*512
    float* attn_out = out + NB * ED;       // attn:    64*1024

    cudaFuncSetAttribute(k_scores, cudaFuncAttributeMaxDynamicSharedMemorySize,
                         DYN_SMEM_BYTES);

    k_prep   <<<ED + NF + NB, 128>>>(query, W_query, W_key, W_loc_proj);
    k_scores <<<dim3(NT / 128, NB), 256, DYN_SMEM_BYTES>>>(keys, awc, W_loc_conv,
                                                           W_attn, mask);
    k_softmax<<<NB, 256>>>(attn_out);
    k_av     <<<dim3(4, NB), 256>>>(values, attn_out);
    k_context<<<dim3(4, NB), 128>>>(W_value, ctx_out);
}

// round 6
// speedup vs baseline: 2.8927x; 1.3073x over previous
#include <cuda_runtime.h>
#include <cuda_bf16.h>
#include <math.h>
#include <stdint.h>

// Problem constants
#define NB   64
#define NT   1024
#define AD   128
#define RD   1024
#define ED   512
#define NF   32
#define KSZ  31
#define PADW 15

#define KTOT 544          // 512 keys + 32 loc features
#define NCH  17           // 17 chunks of K=32
#define TM   128          // t rows per CTA tile

// Tile strides (bytes): 32 bf16 data + 8 pad = 80B rows.
// 80/4 = 20 banks/row -> ldmatrix rows hit distinct 4-bank groups; 16B-multiple for cp.async.
#define TSTRIDE 80
#define TILE_B  (128 * TSTRIDE)             // 10240 B per tile
#define DYN_BYTES (4 * TILE_B)              // A0,A1,B0,B1

// ---------------- device scratch ----------------
__device__ __nv_bfloat16 g_Wbf[AD][KTOT];   // B operand [a][k] bf16
__device__ float g_qproj[NB][AD];
__device__ float g_scores[NB][NT];
__device__ float g_partial[NB][16][ED];

// ---------------- helpers ----------------
__device__ __forceinline__ uint32_t smem_u32(const void* p) {
    uint32_t a;
    asm("{ .reg .u64 t; cvta.to.shared.u64 t, %1; cvt.u32.u64 %0, t; }"
        : "=r"(a) : "l"(p));
    return a;
}
__device__ __forceinline__ void sts64(uint32_t a, uint32_t x, uint32_t y) {
    asm volatile("st.shared.v2.b32 [%0], {%1,%2};" :: "r"(a), "r"(x), "r"(y));
}
__device__ __forceinline__ void sts32(uint32_t a, uint32_t x) {
    asm volatile("st.shared.b32 [%0], %1;" :: "r"(a), "r"(x));
}
__device__ __forceinline__ void cp16(uint32_t dst, const void* src) {
    asm volatile("cp.async.ca.shared.global [%0], [%1], 16;" :: "r"(dst), "l"(src));
}
__device__ __forceinline__ void ldsm4(uint32_t r[4], uint32_t addr) {
    asm volatile("ldmatrix.sync.aligned.m8n8.x4.shared.b16 {%0,%1,%2,%3}, [%4];"
                 : "=r"(r[0]), "=r"(r[1]), "=r"(r[2]), "=r"(r[3]) : "r"(addr));
}
__device__ __forceinline__ void mma_bf16(float d[4], const uint32_t a[4],
                                         uint32_t b0, uint32_t b1) {
    asm volatile(
        "mma.sync.aligned.m16n8k16.row.col.f32.bf16.bf16.f32 "
        "{%0,%1,%2,%3}, {%4,%5,%6,%7}, {%8,%9}, {%0,%1,%2,%3};"
        : "+f"(d[0]), "+f"(d[1]), "+f"(d[2]), "+f"(d[3])
        : "r"(a[0]), "r"(a[1]), "r"(a[2]), "r"(a[3]), "r"(b0), "r"(b1));
}
__device__ __forceinline__ uint32_t pack_bf2(float x, float y) {
    __nv_bfloat162 p = __float22bfloat162_rn(make_float2(x, y));
    return *(uint32_t*)&p;
}

// ---------------------------------------------------------------------------
// Prep: blocks [0,AD) build g_Wbf rows; blocks [AD, AD+NB) do qproj.
__global__ __launch_bounds__(128) void k_prep(const float* __restrict__ query,
                                              const float* __restrict__ W_query,
                                              const float* __restrict__ W_key,
                                              const float* __restrict__ W_loc_proj) {
    int tid = threadIdx.x;
    if (blockIdx.x < AD) {
        int a = blockIdx.x;
        for (int k = tid; k < KTOT; k += 128) {
            float v = (k < ED) ? W_key[a * ED + k] : W_loc_proj[a * NF + (k - ED)];
            g_Wbf[a][k] = __float2bfloat16(v);
        }
        return;
    }
    __shared__ float q_s[RD];
    int b = blockIdx.x - AD;
    #pragma unroll
    for (int i = 0; i < RD / 128; i++)
        q_s[i * 128 + tid] = query[b * RD + i * 128 + tid];
    __syncthreads();
    const float4* wr = (const float4*)(W_query + (size_t)tid * RD);
    float acc = 0.f;
    #pragma unroll 8
    for (int e4 = 0; e4 < RD / 4; e4++) {
        float4 w = wr[e4];
        float4 q = *(const float4*)&q_s[e4 * 4];
        acc += w.x * q.x + w.y * q.y + w.z * q.z + w.w * q.w;
    }
    g_qproj[b][tid] = acc;
}

// ---------------------------------------------------------------------------
// Scores: bf16 m16n8k16 mma + ldmatrix, 2-stage pipeline,
// fused conv-loc chunk + tanh/W_attn/mask epilogue.
__global__ __launch_bounds__(256, 2) void k_scores(
    const float* __restrict__ keys,
    const float* __restrict__ awc,
    const float* __restrict__ W_loc_conv,
    const float* __restrict__ W_attn,
    const unsigned char* __restrict__ mask)
{
    extern __shared__ char dsm[];
    __shared__ float awc_s[158];
    __shared__ float Wc_s[NF][KSZ];
    __shared__ float qp_s[AD];
    __shared__ float wattn_s[AD];
    __shared__ float sred[2][128];

    const int b   = blockIdx.y;
    const int t0  = blockIdx.x * TM;
    const int tid = threadIdx.x;
    const int lane = tid & 31, w = tid >> 5;
    const int g = lane >> 2, tg = lane & 3;
    const int Mb = (w & 3) * 32;       // warp t base
    const int Nb = (w >> 2) * 64;      // warp a base

    const uint32_t base = smem_u32(dsm);
    const uint32_t Aoff[2] = { 0u, (uint32_t)TILE_B };
    const uint32_t Boff[2] = { 2u * TILE_B, 3u * TILE_B };

    // ldmatrix lane addressing
    const int lm = lane & 15;                 // row within 16
    const int lkb = (lane >> 4) * 16;         // 16B sub-block (k 8 elems)
    const int bn = (lane & 7) + ((lane >> 4) << 3);   // B n within 16-tile
    const int bkb = ((lane >> 3) & 1) * 16;           // B k sub-block bytes

    // stage small operands
    if (tid < 158) {
        int gi = t0 - PADW + tid;
        awc_s[tid] = (gi >= 0 && gi < NT) ? awc[b * NT + gi] : 0.f;
    }
    if (tid < AD) { qp_s[tid] = g_qproj[b][tid]; wattn_s[tid] = W_attn[tid]; }
    for (int i = tid; i < NF * KSZ; i += 256)
        Wc_s[i / KSZ][i % KSZ] = W_loc_conv[i];

    // A staging/store mapping: thread j-th float4 -> row r, elem col kq
    const int ar = tid >> 3;            // rows 0..31 (+32 per j)
    const int akq = (tid & 7) << 2;     // 0,4,..28
    const float* kptr = keys + ((size_t)(b * NT + t0 + ar)) * ED + akq;

    // B cp mapping
    const int bnrow = tid >> 2;         // rows 0..63 (+64 per j)
    const int bur = tid & 3;            // 16B unit in row

    float4 ka[4];

    // prologue: stage keys chunk 0, cp B chunk 0
    #pragma unroll
    for (int j = 0; j < 4; j++)
        ka[j] = *(const float4*)(kptr + (size_t)(32 * j) * ED);
    #pragma unroll
    for (int j = 0; j < 2; j++)
        cp16(base + Boff[0] + (bnrow + 64 * j) * TSTRIDE + bur * 16,
             &g_Wbf[bnrow + 64 * j][bur * 8]);
    asm volatile("cp.async.commit_group;");

    float acc[2][8][4];
    #pragma unroll
    for (int mt = 0; mt < 2; mt++)
        #pragma unroll
        for (int nt = 0; nt < 8; nt++)
            #pragma unroll
            for (int ci = 0; ci < 4; ci++) acc[mt][nt][ci] = 0.f;

    for (int c = 0; c < NCH; c++) {
        const int buf = c & 1;
        asm volatile("cp.async.wait_group 0;");
        __syncthreads();                      // buffers free + B(c) visible

        // ---- store A(c) ----
        if (c < 16) {
            #pragma unroll
            for (int j = 0; j < 4; j++) {
                uint32_t p0 = pack_bf2(ka[j].x, ka[j].y);
                uint32_t p1 = pack_bf2(ka[j].z, ka[j].w);
                sts64(base + Aoff[buf] + (ar + 32 * j) * TSTRIDE + akq * 2, p0, p1);
            }
        } else {
            // conv loc-feature chunk: 128 rows x 32 filters
            #pragma unroll
            for (int j = 0; j < 8; j++) {
                int pidx = tid + 256 * j;
                int r = pidx >> 4, f = (pidx & 15) << 1;
                float s0 = 0.f, s1 = 0.f;
                #pragma unroll
                for (int k = 0; k < KSZ; k++) {
                    float av = awc_s[r + k];
                    s0 += av * Wc_s[f][k];
                    s1 += av * Wc_s[f + 1][k];
                }
                sts32(base + Aoff[buf] + r * TSTRIDE + f * 2, pack_bf2(s0, s1));
            }
        }

        // ---- prefetch next chunk ----
        if (c + 1 < 16) {
            #pragma unroll
            for (int j = 0; j < 4; j++)
                ka[j] = *(const float4*)(kptr + (size_t)(32 * j) * ED + (c + 1) * 32);
        }
        if (c + 1 < NCH) {
            #pragma unroll
            for (int j = 0; j < 2; j++)
                cp16(base + Boff[(c + 1) & 1] + (bnrow + 64 * j) * TSTRIDE + bur * 16,
                     &g_Wbf[bnrow + 64 * j][(c + 1) * 32 + bur * 8]);
        }
        asm volatile("cp.async.commit_group;");
        __syncthreads();                      // A(c) visible to all warps

        // ---- mma on chunk c: 2 k16 steps ----
        const uint32_t Ab = base + Aoff[buf];
        const uint32_t Bb = base + Boff[buf];
        #pragma unroll
        for (int k16 = 0; k16 < 2; k16++) {
            uint32_t a[2][4];
            #pragma unroll
            for (int mt = 0; mt < 2; mt++)
                ldsm4(a[mt], Ab + (Mb + mt * 16 + lm) * TSTRIDE + k16 * 32 + lkb);
            #pragma unroll
            for (int g16 = 0; g16 < 4; g16++) {
                uint32_t bb[4];
                ldsm4(bb, Bb + (Nb + g16 * 16 + bn) * TSTRIDE + k16 * 32 + bkb);
                mma_bf16(acc[0][2 * g16],     a[0], bb[0], bb[1]);
                mma_bf16(acc[1][2 * g16],     a[1], bb[0], bb[1]);
                mma_bf16(acc[0][2 * g16 + 1], a[0], bb[2], bb[3]);
                mma_bf16(acc[1][2 * g16 + 1], a[1], bb[2], bb[3]);
            }
        }
    }

    // epilogue: tanh + W_attn dot, reduce over a, mask, store scores
    #pragma unroll
    for (int mt = 0; mt < 2; mt++) {
        #pragma unroll
        for (int h = 0; h < 2; h++) {
            float p = 0.f;
            #pragma unroll
            for (int nt = 0; nt < 8; nt++) {
                int col = Nb + nt * 8 + 2 * tg;
                p += wattn_s[col]     * tanhf(acc[mt][nt][2 * h]     + qp_s[col]);
                p += wattn_s[col + 1] * tanhf(acc[mt][nt][2 * h + 1] + qp_s[col + 1]);
            }
            p += __shfl_xor_sync(0xffffffffu, p, 1);
            p += __shfl_xor_sync(0xffffffffu, p, 2);
            if (tg == 0)
                sred[w >> 2][Mb + mt * 16 + g + 8 * h] = p;
        }
    }
    __syncthreads();
    if (tid < 128) {
        int t = t0 + tid;
        float sc = sred[0][tid] + sred[1][tid];
        if (mask[b * NT + t]) sc = -INFINITY;
        g_scores[b][t] = sc;
    }
}

// ---------------------------------------------------------------------------
__global__ __launch_bounds__(256) void k_softmax(float* __restrict__ attn_out) {
    __shared__ float red[256];
    int b = blockIdx.x, tid = threadIdx.x;
    float v[4];
    float m = -INFINITY;
    #pragma unroll
    for (int i = 0; i < 4; i++) {
        v[i] = g_scores[b][i * 256 + tid];
        m = fmaxf(m, v[i]);
    }
    red[tid] = m; __syncthreads();
    for (int s = 128; s > 0; s >>= 1) {
        if (tid < s) red[tid] = fmaxf(red[tid], red[tid + s]);
        __syncthreads();
    }
    m = red[0]; __syncthreads();
    float sum = 0.f;
    #pragma unroll
    for (int i = 0; i < 4; i++) { v[i] = __expf(v[i] - m); sum += v[i]; }
    red[tid] = sum; __syncthreads();
    for (int s = 128; s > 0; s >>= 1) {
        if (tid < s) red[tid] += red[tid + s];
        __syncthreads();
    }
    float inv = 1.f / red[0];
    #pragma unroll
    for (int i = 0; i < 4; i++)
        attn_out[b * NT + i * 256 + tid] = v[i] * inv;
}

// ---------------------------------------------------------------------------
// attn @ values: 512 blocks, 16 partials per batch. HBM-bound.
__global__ __launch_bounds__(256) void k_av(const float* __restrict__ values,
                                            const float* __restrict__ attn) {
    __shared__ float at_s[128];
    int ts = blockIdx.x, b = blockIdx.y, tid = threadIdx.x;
    if (tid < 128) at_s[tid] = attn[b * NT + ts * 128 + tid];
    __syncthreads();
    int cg = tid & 127, half = tid >> 7;
    const float4* vp = (const float4*)
        (values + ((size_t)(b * NT + ts * 128 + half * 64)) * ED);
    float4 acc = make_float4(0.f, 0.f, 0.f, 0.f);
    #pragma unroll 8
    for (int t = 0; t < 64; t++) {
        float wv = at_s[half * 64 + t];
        float4 v = vp[(size_t)t * (ED / 4) + cg];
        acc.x += wv * v.x; acc.y += wv * v.y;
        acc.z += wv * v.z; acc.w += wv * v.w;
    }
    *(float4*)&g_partial[b][ts * 2 + half][cg * 4] = acc;
}

// ---------------------------------------------------------------------------
__global__ __launch_bounds__(128) void k_context(const float* __restrict__ W_value,
                                                 float* __restrict__ ctx) {
    __shared__ float av_s[ED];
    int fc = blockIdx.x, b = blockIdx.y, tid = threadIdx.x;
    for (int i = tid; i < ED; i += 128) {
        float s = 0.f;
        #pragma unroll
        for (int p = 0; p < 16; p++) s += g_partial[b][p][i];
        av_s[i] = s;
    }
    __syncthreads();
    int f = fc * 128 + tid;
    const float4* wr = (const float4*)(W_value + (size_t)f * ED);
    float acc = 0.f;
    #pragma unroll 8
    for (int e4 = 0; e4 < ED / 4; e4++) {
        float4 wv = wr[e4];
        float4 a = *(const float4*)&av_s[e4 * 4];
        acc += wv.x * a.x + wv.y * a.y + wv.z * a.z + wv.w * a.w;
    }
    ctx[b * ED + f] = acc;
}

// ---------------------------------------------------------------------------
extern "C" void kernel_launch(void* const* d_in, const int* in_sizes, int n_in,
                              void* d_out, int out_size) {
    const float* query        = (const float*)d_in[0];
    const float* keys         = (const float*)d_in[1];
    const float* values       = (const float*)d_in[2];
    const float* awc          = (const float*)d_in[3];
    const unsigned char* mask = (const unsigned char*)d_in[4];
    const float* W_loc_conv   = (const float*)d_in[5];
    const float* W_loc_proj   = (const float*)d_in[6];
    const float* W_query      = (const float*)d_in[7];
    const float* W_key        = (const float*)d_in[8];
    const float* W_value      = (const float*)d_in[9];
    const float* W_attn       = (const float*)d_in[10];

    float* out      = (float*)d_out;
    float* ctx_out  = out;                 // context: 64*512
    float* attn_out = out + NB * ED;       // attn:    64*1024

    cudaFuncSetAttribute(k_scores, cudaFuncAttributeMaxDynamicSharedMemorySize,
                         DYN_BYTES);

    k_prep   <<<AD + NB, 128>>>(query, W_query, W_key, W_loc_proj);
    k_scores <<<dim3(NT / TM, NB), 256, DYN_BYTES>>>(keys, awc, W_loc_conv,
                                                     W_attn, mask);
    k_softmax<<<NB, 256>>>(attn_out);
    k_av     <<<dim3(8, NB), 256>>>(values, attn_out);
    k_context<<<dim3(4, NB), 128>>>(W_value, ctx_out);
}